// round 13
// baseline (speedup 1.0000x reference)
#include <cuda_runtime.h>
#include <cuda_fp16.h>
#include <math.h>
#include <stdint.h>

#define D_MODEL 1024
#define SEQ     2048
#define BATCH   4
#define NH      16
#define DFF     4096
#define MROWS   (BATCH*SEQ)   /* 8192 */

// ---------------- scratch (device globals: allocation-free) ----------------
__device__ __half  g_qkv[MROWS * 3 * D_MODEL];
__device__ float   g_x1 [MROWS * D_MODEL];
__device__ __half  g_ln [MROWS * D_MODEL];
__device__ __half  g_ctx[MROWS * D_MODEL];
__device__ __half  g_h  [MROWS * DFF];
// fp16 weights, SAME layout as input: [K][N]
__device__ __half  g_wq [D_MODEL * 3 * D_MODEL];
__device__ __half  g_wo [D_MODEL * D_MODEL];
__device__ __half  g_w1 [D_MODEL * DFF];
__device__ __half  g_w2 [DFF * D_MODEL];

// ---------------- PTX helpers ----------------
__device__ __forceinline__ uint32_t smem_u32(const void* p) {
    return (uint32_t)__cvta_generic_to_shared(p);
}
__device__ __forceinline__ void cpa16(uint32_t dst, const void* src) {
    asm volatile("cp.async.cg.shared.global [%0], [%1], 16;" :: "r"(dst), "l"(src));
}
__device__ __forceinline__ void cp_commit() { asm volatile("cp.async.commit_group;" ::: "memory"); }
__device__ __forceinline__ void cp_wait2()  { asm volatile("cp.async.wait_group 2;"  ::: "memory"); }
__device__ __forceinline__ void cp_wait1()  { asm volatile("cp.async.wait_group 1;"  ::: "memory"); }
__device__ __forceinline__ void cp_wait0()  { asm volatile("cp.async.wait_group 0;"  ::: "memory"); }

__device__ __forceinline__ void ldsm_x4(uint32_t& r0, uint32_t& r1, uint32_t& r2, uint32_t& r3,
                                        uint32_t addr) {
    asm volatile("ldmatrix.sync.aligned.m8n8.x4.shared.b16 {%0,%1,%2,%3}, [%4];"
                 : "=r"(r0), "=r"(r1), "=r"(r2), "=r"(r3) : "r"(addr));
}
__device__ __forceinline__ void ldsm_x4t(uint32_t& r0, uint32_t& r1, uint32_t& r2, uint32_t& r3,
                                         uint32_t addr) {
    asm volatile("ldmatrix.sync.aligned.m8n8.x4.trans.shared.b16 {%0,%1,%2,%3}, [%4];"
                 : "=r"(r0), "=r"(r1), "=r"(r2), "=r"(r3) : "r"(addr));
}
__device__ __forceinline__ void mma16816h(float* c, uint32_t a0, uint32_t a1, uint32_t a2,
                                          uint32_t a3, uint32_t b0, uint32_t b1) {
    asm volatile("mma.sync.aligned.m16n8k16.row.col.f32.f16.f16.f32 "
                 "{%0,%1,%2,%3}, {%4,%5,%6,%7}, {%8,%9}, {%0,%1,%2,%3};"
                 : "+f"(c[0]), "+f"(c[1]), "+f"(c[2]), "+f"(c[3])
                 : "r"(a0), "r"(a1), "r"(a2), "r"(a3), "r"(b0), "r"(b1));
}
__device__ __forceinline__ float ex2f(float x) {
    float r;
    asm("ex2.approx.f32 %0, %1;" : "=f"(r) : "f"(x));
    return r;
}

// ---------------- misc math ----------------
__device__ __forceinline__ float gelu_tanh(float x) {
    float x3 = x * x * x;
    return 0.5f * x * (1.0f + tanhf(0.7978845608028654f * (x + 0.044715f * x3)));
}
__device__ __forceinline__ uint32_t pack_h2(float a, float b) {
    __half2 t = __floats2half2_rn(a, b);
    return *reinterpret_cast<uint32_t*>(&t);
}

// ================= LayerNorm (warp-per-row) -> fp16 =================
__global__ void __launch_bounds__(256) ln_kernel(
    const float* __restrict__ x, const float* __restrict__ sc,
    const float* __restrict__ bi, __half* __restrict__ y)
{
    const int warp = threadIdx.x >> 5, lane = threadIdx.x & 31;
    const int row = blockIdx.x * 8 + warp;
    const float* xr = x + (size_t)row * D_MODEL;

    float v[32];
    float s = 0.f;
    #pragma unroll
    for (int i = 0; i < 8; i++) {
        const float4 t = *reinterpret_cast<const float4*>(xr + (i * 32 + lane) * 4);
        v[i * 4 + 0] = t.x; v[i * 4 + 1] = t.y; v[i * 4 + 2] = t.z; v[i * 4 + 3] = t.w;
        s += t.x + t.y + t.z + t.w;
    }
    #pragma unroll
    for (int o = 16; o; o >>= 1) s += __shfl_xor_sync(0xffffffffu, s, o);
    const float mu = s * (1.0f / D_MODEL);

    float sq = 0.f;
    #pragma unroll
    for (int i = 0; i < 32; i++) {
        v[i] -= mu;
        sq += v[i] * v[i];
    }
    #pragma unroll
    for (int o = 16; o; o >>= 1) sq += __shfl_xor_sync(0xffffffffu, sq, o);
    const float inv = rsqrtf(sq * (1.0f / D_MODEL) + 1e-6f);

    __half* yr = y + (size_t)row * D_MODEL;
    #pragma unroll
    for (int i = 0; i < 8; i++) {
        const int c = (i * 32 + lane) * 4;
        const float4 scv = *reinterpret_cast<const float4*>(sc + c);
        const float4 biv = *reinterpret_cast<const float4*>(bi + c);
        *reinterpret_cast<__half2*>(yr + c) =
            __floats2half2_rn(v[i*4+0] * inv * scv.x + biv.x, v[i*4+1] * inv * scv.y + biv.y);
        *reinterpret_cast<__half2*>(yr + c + 2) =
            __floats2half2_rn(v[i*4+2] * inv * scv.z + biv.z, v[i*4+3] * inv * scv.w + biv.w);
    }
}

// ========== merged weight convert: fp32 -> fp16, same [K][N] layout ==========
#define WQ4 (D_MODEL * 3 * D_MODEL / 4)
#define WO4 (D_MODEL * D_MODEL / 4)
#define W14 (D_MODEL * DFF / 4)
#define W24 (DFF * D_MODEL / 4)
#define WTOT4 (WQ4 + WO4 + W14 + W24)

__global__ void __launch_bounds__(256) convert_all(
    const float* __restrict__ wq, __half* __restrict__ oq,
    const float* __restrict__ wo, __half* __restrict__ oo,
    const float* __restrict__ w1, __half* __restrict__ o1,
    const float* __restrict__ w2, __half* __restrict__ o2)
{
    int i = blockIdx.x * 256 + threadIdx.x;
    if (i >= WTOT4) return;
    const float* src; __half* dst; int j = i;
    if (j < WQ4) { src = wq; dst = oq; }
    else if ((j -= WQ4) < WO4) { src = wo; dst = oo; }
    else if ((j -= WO4) < W14) { src = w1; dst = o1; }
    else { j -= W14; src = w2; dst = o2; }
    float4 v = reinterpret_cast<const float4*>(src)[j];
    *reinterpret_cast<__half2*>(dst + (size_t)j * 4)     = __floats2half2_rn(v.x, v.y);
    *reinterpret_cast<__half2*>(dst + (size_t)j * 4 + 2) = __floats2half2_rn(v.z, v.w);
}

// ================= fp16 GEMM via mma.sync (unchanged) =================
#define KC 32
#define APAD 40
#define BROW 272
#define OFF_A 0
#define OFF_B (128 * APAD * 2)
#define STAGE_BYTES (OFF_B + KC * BROW)
#define NSTAGE 4
#define GEMM_SMEM (NSTAGE * STAGE_BYTES)

__device__ __forceinline__ void load_chunk_h(
    uint32_t sbase, const __half* __restrict__ A, const __half* __restrict__ W,
    int m0, int n0, int N, int K, int k0, int tid)
{
    #pragma unroll
    for (int j = 0; j < 2; j++) {
        int idx = tid + j * 256;
        int r = idx >> 2, sg = idx & 3;
        cpa16(sbase + OFF_A + (uint32_t)(r * (APAD * 2) + sg * 16),
              A + (size_t)(m0 + r) * K + k0 + sg * 8);
    }
    #pragma unroll
    for (int j = 0; j < 2; j++) {
        int idx = tid + j * 256;
        int r = idx >> 4, sg = idx & 15;
        cpa16(sbase + OFF_B + (uint32_t)(r * BROW + sg * 16),
              W + (size_t)(k0 + r) * N + n0 + sg * 8);
    }
}

template<bool GELU_, bool RES_, bool HALFOUT>
__global__ void __launch_bounds__(256, 2) gemm_h(
    const __half* __restrict__ A, const __half* __restrict__ W,
    const float* __restrict__ bias, const float* __restrict__ Res,
    float* __restrict__ Cf, __half* __restrict__ Ch,
    int M, int N, int K)
{
    extern __shared__ char smem[];
    const uint32_t sb = smem_u32(smem);
    const int tid = threadIdx.x;
    const int wid = tid >> 5, lane = tid & 31;
    const int m0 = blockIdx.y * 128, n0 = blockIdx.x * 128;
    const int wm = (wid >> 2) * 64;
    const int wn = (wid & 3) * 32;

    const int a_r = lane & 15;
    const int a_c = (lane & 16) ? 8 : 0;
    const int b_row  = lane & 15;
    const int b_col8 = (lane & 16) ? 8 : 0;

    float c[4][4][4];
    #pragma unroll
    for (int i = 0; i < 4; i++)
        #pragma unroll
        for (int j = 0; j < 4; j++)
            #pragma unroll
            for (int e = 0; e < 4; e++) c[i][j][e] = 0.f;

    load_chunk_h(sb,                   A, W, m0, n0, N, K, 0 * KC, tid);
    cp_commit();
    load_chunk_h(sb + 1 * STAGE_BYTES, A, W, m0, n0, N, K, 1 * KC, tid);
    cp_commit();
    load_chunk_h(sb + 2 * STAGE_BYTES, A, W, m0, n0, N, K, 2 * KC, tid);
    cp_commit();

    const int NC = K / KC;
    for (int i = 0; i < NC; i++) {
        if (i <= NC - 3) cp_wait2();
        else if (i == NC - 2) cp_wait1();
        else cp_wait0();
        __syncthreads();
        if (i + 3 < NC) {
            load_chunk_h(sb + ((i + 3) & 3) * STAGE_BYTES, A, W, m0, n0, N, K, (i + 3) * KC, tid);
            cp_commit();
        }
        const uint32_t st = sb + (i & 3) * STAGE_BYTES;
        const uint32_t aA = st + OFF_A + (wm + a_r) * (APAD * 2) + a_c * 2;
        #pragma unroll
        for (int kk = 0; kk < KC; kk += 16) {
            uint32_t af[4][4], bf[2][4];
            #pragma unroll
            for (int mt = 0; mt < 4; mt++)
                ldsm_x4(af[mt][0], af[mt][1], af[mt][2], af[mt][3],
                        aA + mt * 16 * (APAD * 2) + kk * 2);
            #pragma unroll
            for (int g = 0; g < 2; g++)
                ldsm_x4t(bf[g][0], bf[g][1], bf[g][2], bf[g][3],
                         st + OFF_B + (uint32_t)((kk + b_row) * BROW
                                                 + (wn + g * 16 + b_col8) * 2));
            #pragma unroll
            for (int mt = 0; mt < 4; mt++)
                #pragma unroll
                for (int nt = 0; nt < 4; nt++) {
                    const int g = nt >> 1, p = (nt & 1) * 2;
                    mma16816h(c[mt][nt], af[mt][0], af[mt][1], af[mt][2], af[mt][3],
                              bf[g][p], bf[g][p + 1]);
                }
        }
    }

    const int t4 = lane >> 2, cp2 = (lane & 3) * 2;
    #pragma unroll
    for (int mt = 0; mt < 4; mt++) {
        #pragma unroll
        for (int half = 0; half < 2; half++) {
            const int row = m0 + wm + mt * 16 + t4 + half * 8;
            #pragma unroll
            for (int nt = 0; nt < 4; nt++) {
                const int col = n0 + wn + nt * 8 + cp2;
                float v0 = c[mt][nt][half * 2 + 0];
                float v1 = c[mt][nt][half * 2 + 1];
                const float2 bv = *reinterpret_cast<const float2*>(bias + col);
                v0 += bv.x; v1 += bv.y;
                if (GELU_) { v0 = gelu_tanh(v0); v1 = gelu_tanh(v1); }
                if (RES_) {
                    const float2 rv = *reinterpret_cast<const float2*>(
                        Res + (size_t)row * N + col);
                    v0 += rv.x; v1 += rv.y;
                }
                const size_t oof = (size_t)row * N + col;
                if (HALFOUT) {
                    *reinterpret_cast<__half2*>(Ch + oof) = __floats2half2_rn(v0, v1);
                } else {
                    float2 ov; ov.x = v0; ov.y = v1;
                    *reinterpret_cast<float2*>(Cf + oof) = ov;
                }
            }
        }
    }
}

// ============ Flash attention: 128-q-row CTA, 8 warps, shared K/V ============
#define FRP 72
#define FQO 0                               /* Q: 128 rows */
#define FKO(s) ((128 + 128 * (s)) * FRP)    /* K buffer s (64 rows) */
#define FVO(s) ((192 + 128 * (s)) * FRP)    /* V buffer s (64 rows) */
#define FA_SMEM (384 * FRP * 2)             /* 55296 bytes */

// 64-row tile, 256 threads: 512 cpa16 -> 2/thread
__device__ __forceinline__ void fa_load64(uint32_t dst, const __half* __restrict__ src, int tid)
{
    #pragma unroll
    for (int j = 0; j < 2; j++) {
        int idx = tid + j * 256;
        int r = idx >> 3, sg = idx & 7;
        cpa16(dst + (uint32_t)(r * (FRP * 2) + sg * 16),
              src + (size_t)r * 3072 + sg * 8);
    }
}
// 128-row tile (Q), 256 threads: 1024 cpa16 -> 4/thread
__device__ __forceinline__ void fa_load128(uint32_t dst, const __half* __restrict__ src, int tid)
{
    #pragma unroll
    for (int j = 0; j < 4; j++) {
        int idx = tid + j * 256;
        int r = idx >> 3, sg = idx & 7;
        cpa16(dst + (uint32_t)(r * (FRP * 2) + sg * 16),
              src + (size_t)r * 3072 + sg * 8);
    }
}

__global__ void __launch_bounds__(256) fa_kernel(
    const __half* __restrict__ qkv, __half* __restrict__ ctx)
{
    // longest-first: qtile descending with launch index
    const int qtile = (SEQ / 128 - 1) - blockIdx.x;
    const int h = blockIdx.y, b = blockIdx.z;
    const int q0 = qtile * 128;
    extern __shared__ __half fsm[];
    const uint32_t sbase = smem_u32(fsm);
    const int tid = threadIdx.x;
    const int warp = tid >> 5, lane = tid & 31;
    const int t4 = lane >> 2, cp = (lane & 3) * 2;

    fa_load128(sbase + FQO * 2, qkv + ((size_t)(b * SEQ + q0) * 3) * 1024 + h * 64, tid);
    fa_load64(sbase + FKO(0) * 2, qkv + ((size_t)(b * SEQ) * 3 + 1) * 1024 + h * 64, tid);
    fa_load64(sbase + FVO(0) * 2, qkv + ((size_t)(b * SEQ) * 3 + 2) * 1024 + h * 64, tid);
    cp_commit();

    const int a_r = lane & 15;
    const int a_c = (lane & 16) ? 8 : 0;
    const int b_r = (lane & 7) + ((lane & 16) ? 8 : 0);
    const int b_c = (lane & 8) ? 8 : 0;

    float o[8][4];
    #pragma unroll
    for (int i = 0; i < 8; i++)
        #pragma unroll
        for (int e = 0; e < 4; e++) o[i][e] = 0.f;
    float m0r = -1e30f, m1r = -1e30f, l0r = 0.f, l1r = 0.f;

    const int row0 = q0 + warp * 16 + t4;   // this warp owns q rows [q0+warp*16, +16)
    const int row1 = row0 + 8;

    uint32_t qf[4][4];
    bool qloaded = false;
    const __half2 qsc = __float2half2_rn(0.125f * 1.44269504f);

    const int NT = 2 * qtile + 2;   // k-tiles 0 .. 2*qtile+1
    for (int kt = 0; kt < NT; kt++) {
        if (kt + 1 < NT) {
            fa_load64(sbase + FKO((kt + 1) & 1) * 2,
                      qkv + ((size_t)(b * SEQ + (kt + 1) * 64) * 3 + 1) * 1024 + h * 64, tid);
            fa_load64(sbase + FVO((kt + 1) & 1) * 2,
                      qkv + ((size_t)(b * SEQ + (kt + 1) * 64) * 3 + 2) * 1024 + h * 64, tid);
            cp_commit();
            cp_wait1();
        } else {
            cp_wait0();
        }
        __syncthreads();

        if (!qloaded) {
            qloaded = true;
            #pragma unroll
            for (int kk = 0; kk < 4; kk++) {
                ldsm_x4(qf[kk][0], qf[kk][1], qf[kk][2], qf[kk][3],
                        sbase + (uint32_t)(((warp * 16 + a_r) * FRP + kk * 16 + a_c) * 2) + FQO * 2);
                #pragma unroll
                for (int r = 0; r < 4; r++) {
                    __half2 hv = *reinterpret_cast<__half2*>(&qf[kk][r]);
                    hv = __hmul2(hv, qsc);
                    qf[kk][r] = *reinterpret_cast<uint32_t*>(&hv);
                }
            }
        }

        const uint32_t kb = sbase + FKO(kt & 1) * 2;
        const uint32_t vb = sbase + FVO(kt & 1) * 2;

        // ---- S = Q K^T ----
        float c[8][4];
        #pragma unroll
        for (int i = 0; i < 8; i++)
            #pragma unroll
            for (int e = 0; e < 4; e++) c[i][e] = 0.f;
        #pragma unroll
        for (int kk = 0; kk < 4; kk++) {
            uint32_t kf[4][4];
            #pragma unroll
            for (int g = 0; g < 4; g++)
                ldsm_x4(kf[g][0], kf[g][1], kf[g][2], kf[g][3],
                        kb + (uint32_t)(((g * 16 + b_r) * FRP + kk * 16 + b_c) * 2));
            #pragma unroll
            for (int nt = 0; nt < 8; nt++) {
                const int g = nt >> 1, p = (nt & 1) * 2;
                mma16816h(c[nt], qf[kk][0], qf[kk][1], qf[kk][2], qf[kk][3],
                          kf[g][p], kf[g][p + 1]);
            }
        }

        // ---- causal mask (gated: only last two k-tiles can exceed rows) ----
        if (kt >= 2 * qtile) {
            #pragma unroll
            for (int nt = 0; nt < 8; nt++) {
                const int colb = kt * 64 + nt * 8 + cp;
                #pragma unroll
                for (int e = 0; e < 4; e++) {
                    const int col = colb + (e & 1);
                    const int row = (e < 2) ? row0 : row1;
                    if (col > row) c[nt][e] = -1e30f;
                }
            }
        }

        // ---- online softmax (base-2) ----
        float mx0 = -1e30f, mx1 = -1e30f;
        #pragma unroll
        for (int nt = 0; nt < 8; nt++) {
            mx0 = fmaxf(mx0, fmaxf(c[nt][0], c[nt][1]));
            mx1 = fmaxf(mx1, fmaxf(c[nt][2], c[nt][3]));
        }
        mx0 = fmaxf(mx0, __shfl_xor_sync(0xffffffffu, mx0, 1));
        mx0 = fmaxf(mx0, __shfl_xor_sync(0xffffffffu, mx0, 2));
        mx1 = fmaxf(mx1, __shfl_xor_sync(0xffffffffu, mx1, 1));
        mx1 = fmaxf(mx1, __shfl_xor_sync(0xffffffffu, mx1, 2));
        const float mn0 = fmaxf(m0r, mx0), mn1 = fmaxf(m1r, mx1);
        const float al0 = ex2f(m0r - mn0), al1 = ex2f(m1r - mn1);
        m0r = mn0; m1r = mn1;
        float sum0 = 0.f, sum1 = 0.f;
        #pragma unroll
        for (int nt = 0; nt < 8; nt++) {
            float p0 = ex2f(c[nt][0] - mn0);
            float p1 = ex2f(c[nt][1] - mn0);
            float p2 = ex2f(c[nt][2] - mn1);
            float p3 = ex2f(c[nt][3] - mn1);
            c[nt][0] = p0; c[nt][1] = p1; c[nt][2] = p2; c[nt][3] = p3;
            sum0 += p0 + p1; sum1 += p2 + p3;
        }
        sum0 += __shfl_xor_sync(0xffffffffu, sum0, 1);
        sum0 += __shfl_xor_sync(0xffffffffu, sum0, 2);
        sum1 += __shfl_xor_sync(0xffffffffu, sum1, 1);
        sum1 += __shfl_xor_sync(0xffffffffu, sum1, 2);
        l0r = l0r * al0 + sum0;
        l1r = l1r * al1 + sum1;
        #pragma unroll
        for (int dt = 0; dt < 8; dt++) {
            o[dt][0] *= al0; o[dt][1] *= al0;
            o[dt][2] *= al1; o[dt][3] *= al1;
        }

        // ---- O += P V ----
        #pragma unroll
        for (int kt2 = 0; kt2 < 4; kt2++) {
            uint32_t pa[4];
            #pragma unroll
            for (int r = 0; r < 4; r++) {
                const int nt = 2 * kt2 + (r >> 1);
                const int e = (r & 1) * 2;
                pa[r] = pack_h2(c[nt][e], c[nt][e + 1]);
            }
            #pragma unroll
            for (int g2 = 0; g2 < 4; g2++) {
                uint32_t vr = vb +
                    (uint32_t)(((kt2 * 16 + ((lane & 8) ? 8 : 0) + (lane & 7)) * FRP
                                + g2 * 16 + ((lane & 16) ? 8 : 0)) * 2);
                uint32_t vf[4];
                ldsm_x4t(vf[0], vf[1], vf[2], vf[3], vr);
                mma16816h(o[2 * g2],     pa[0], pa[1], pa[2], pa[3], vf[0], vf[1]);
                mma16816h(o[2 * g2 + 1], pa[0], pa[1], pa[2], pa[3], vf[2], vf[3]);
            }
        }
        __syncthreads();
    }

    const float inv0 = 1.0f / l0r, inv1 = 1.0f / l1r;
    #pragma unroll
    for (int dt = 0; dt < 8; dt++) {
        const int col = h * 64 + dt * 8 + cp;
        *reinterpret_cast<__half2*>(ctx + (size_t)(b * SEQ + row0) * 1024 + col) =
            __floats2half2_rn(o[dt][0] * inv0, o[dt][1] * inv0);
        *reinterpret_cast<__half2*>(ctx + (size_t)(b * SEQ + row1) * 1024 + col) =
            __floats2half2_rn(o[dt][2] * inv1, o[dt][3] * inv1);
    }
}

// ================= launch =================
extern "C" void kernel_launch(void* const* d_in, const int* in_sizes, int n_in,
                              void* d_out, int out_size)
{
    const float* x      = (const float*)d_in[0];
    const float* w_qkv  = (const float*)d_in[1];
    const float* b_qkv  = (const float*)d_in[2];
    const float* w_out  = (const float*)d_in[3];
    const float* b_out  = (const float*)d_in[4];
    const float* w_fc1  = (const float*)d_in[5];
    const float* b_fc1  = (const float*)d_in[6];
    const float* w_fc2  = (const float*)d_in[7];
    const float* b_fc2  = (const float*)d_in[8];
    const float* ln1s   = (const float*)d_in[9];
    const float* ln1b   = (const float*)d_in[10];
    const float* ln2s   = (const float*)d_in[11];
    const float* ln2b   = (const float*)d_in[12];
    float* out = (float*)d_out;

    float *p_x1;
    __half *p_qkv, *p_ln, *p_ctx, *p_h, *p_wq, *p_wo, *p_w1, *p_w2;
    cudaGetSymbolAddress((void**)&p_qkv, g_qkv);
    cudaGetSymbolAddress((void**)&p_x1,  g_x1);
    cudaGetSymbolAddress((void**)&p_ln,  g_ln);
    cudaGetSymbolAddress((void**)&p_ctx, g_ctx);
    cudaGetSymbolAddress((void**)&p_h,   g_h);
    cudaGetSymbolAddress((void**)&p_wq,  g_wq);
    cudaGetSymbolAddress((void**)&p_wo,  g_wo);
    cudaGetSymbolAddress((void**)&p_w1,  g_w1);
    cudaGetSymbolAddress((void**)&p_w2,  g_w2);

    cudaFuncSetAttribute(gemm_h<false, false, true>,
                         cudaFuncAttributeMaxDynamicSharedMemorySize, GEMM_SMEM);
    cudaFuncSetAttribute(gemm_h<false, true, false>,
                         cudaFuncAttributeMaxDynamicSharedMemorySize, GEMM_SMEM);
    cudaFuncSetAttribute(gemm_h<true, false, true>,
                         cudaFuncAttributeMaxDynamicSharedMemorySize, GEMM_SMEM);
    cudaFuncSetAttribute(fa_kernel,
                         cudaFuncAttributeMaxDynamicSharedMemorySize, FA_SMEM);

    // 0) all weight converts in ONE launch
    convert_all<<<(WTOT4 + 255) / 256, 256>>>(w_qkv, p_wq, w_out, p_wo,
                                              w_fc1, p_w1, w_fc2, p_w2);
    // 1) LN1 -> fp16
    ln_kernel<<<MROWS / 8, 256>>>(x, ln1s, ln1b, p_ln);
    // 2) QKV projection -> fp16
    gemm_h<false, false, true><<<dim3(3072 / 128, MROWS / 128), 256, GEMM_SMEM>>>(
        p_ln, p_wq, b_qkv, nullptr, nullptr, p_qkv, MROWS, 3072, 1024);
    // 3) flash attention -> fp16 ctx (128-q-row CTAs)
    fa_kernel<<<dim3(SEQ / 128, NH, BATCH), 256, FA_SMEM>>>(p_qkv, p_ctx);
    // 4) out projection + residual(x) -> fp32 x1
    gemm_h<false, true, false><<<dim3(1024 / 128, MROWS / 128), 256, GEMM_SMEM>>>(
        p_ctx, p_wo, b_out, x, p_x1, nullptr, MROWS, 1024, 1024);
    // 5) LN2 -> fp16
    ln_kernel<<<MROWS / 8, 256>>>(p_x1, ln2s, ln2b, p_ln);
    // 6) FC1 + GELU -> fp16
    gemm_h<true, false, true><<<dim3(4096 / 128, MROWS / 128), 256, GEMM_SMEM>>>(
        p_ln, p_w1, b_fc1, nullptr, nullptr, p_h, MROWS, 4096, 1024);
    // 7) FC2 + residual(x1) -> out (fp32)
    gemm_h<false, true, false><<<dim3(1024 / 128, MROWS / 128), 256, GEMM_SMEM>>>(
        p_h, p_w2, b_fc2, p_x1, out, nullptr, MROWS, 1024, 4096);
}

// round 15
// speedup vs baseline: 1.0239x; 1.0239x over previous
#include <cuda_runtime.h>
#include <cuda_fp16.h>
#include <math.h>
#include <stdint.h>

#define D_MODEL 1024
#define SEQ     2048
#define BATCH   4
#define NH      16
#define DFF     4096
#define MROWS   (BATCH*SEQ)   /* 8192 */

// ---------------- scratch (device globals: allocation-free) ----------------
__device__ __half  g_qkv[MROWS * 3 * D_MODEL];
__device__ float   g_x1 [MROWS * D_MODEL];
__device__ __half  g_ln [MROWS * D_MODEL];
__device__ __half  g_ctx[MROWS * D_MODEL];
__device__ __half  g_h  [MROWS * DFF];
// fp16 weights, SAME layout as input: [K][N]
__device__ __half  g_wq [D_MODEL * 3 * D_MODEL];
__device__ __half  g_wo [D_MODEL * D_MODEL];
__device__ __half  g_w1 [D_MODEL * DFF];
__device__ __half  g_w2 [DFF * D_MODEL];

// ---------------- PTX helpers ----------------
__device__ __forceinline__ uint32_t smem_u32(const void* p) {
    return (uint32_t)__cvta_generic_to_shared(p);
}
__device__ __forceinline__ void cpa16(uint32_t dst, const void* src) {
    asm volatile("cp.async.cg.shared.global [%0], [%1], 16;" :: "r"(dst), "l"(src));
}
__device__ __forceinline__ void cp_commit() { asm volatile("cp.async.commit_group;" ::: "memory"); }
__device__ __forceinline__ void cp_wait1()  { asm volatile("cp.async.wait_group 1;"  ::: "memory"); }
__device__ __forceinline__ void cp_wait0()  { asm volatile("cp.async.wait_group 0;"  ::: "memory"); }

__device__ __forceinline__ void ldsm_x4(uint32_t& r0, uint32_t& r1, uint32_t& r2, uint32_t& r3,
                                        uint32_t addr) {
    asm volatile("ldmatrix.sync.aligned.m8n8.x4.shared.b16 {%0,%1,%2,%3}, [%4];"
                 : "=r"(r0), "=r"(r1), "=r"(r2), "=r"(r3) : "r"(addr));
}
__device__ __forceinline__ void ldsm_x4t(uint32_t& r0, uint32_t& r1, uint32_t& r2, uint32_t& r3,
                                         uint32_t addr) {
    asm volatile("ldmatrix.sync.aligned.m8n8.x4.trans.shared.b16 {%0,%1,%2,%3}, [%4];"
                 : "=r"(r0), "=r"(r1), "=r"(r2), "=r"(r3) : "r"(addr));
}
__device__ __forceinline__ void mma16816h(float* c, uint32_t a0, uint32_t a1, uint32_t a2,
                                          uint32_t a3, uint32_t b0, uint32_t b1) {
    asm volatile("mma.sync.aligned.m16n8k16.row.col.f32.f16.f16.f32 "
                 "{%0,%1,%2,%3}, {%4,%5,%6,%7}, {%8,%9}, {%0,%1,%2,%3};"
                 : "+f"(c[0]), "+f"(c[1]), "+f"(c[2]), "+f"(c[3])
                 : "r"(a0), "r"(a1), "r"(a2), "r"(a3), "r"(b0), "r"(b1));
}
__device__ __forceinline__ float ex2f(float x) {
    float r;
    asm("ex2.approx.f32 %0, %1;" : "=f"(r) : "f"(x));
    return r;
}

// ---------------- misc math ----------------
__device__ __forceinline__ float gelu_tanh(float x) {
    float x3 = x * x * x;
    return 0.5f * x * (1.0f + tanhf(0.7978845608028654f * (x + 0.044715f * x3)));
}
__device__ __forceinline__ uint32_t pack_h2(float a, float b) {
    __half2 t = __floats2half2_rn(a, b);
    return *reinterpret_cast<uint32_t*>(&t);
}

// ================= LayerNorm (warp-per-row) -> fp16 =================
__global__ void __launch_bounds__(256) ln_kernel(
    const float* __restrict__ x, const float* __restrict__ sc,
    const float* __restrict__ bi, __half* __restrict__ y)
{
    const int warp = threadIdx.x >> 5, lane = threadIdx.x & 31;
    const int row = blockIdx.x * 8 + warp;
    const float* xr = x + (size_t)row * D_MODEL;

    float v[32];
    float s = 0.f;
    #pragma unroll
    for (int i = 0; i < 8; i++) {
        const float4 t = *reinterpret_cast<const float4*>(xr + (i * 32 + lane) * 4);
        v[i * 4 + 0] = t.x; v[i * 4 + 1] = t.y; v[i * 4 + 2] = t.z; v[i * 4 + 3] = t.w;
        s += t.x + t.y + t.z + t.w;
    }
    #pragma unroll
    for (int o = 16; o; o >>= 1) s += __shfl_xor_sync(0xffffffffu, s, o);
    const float mu = s * (1.0f / D_MODEL);

    float sq = 0.f;
    #pragma unroll
    for (int i = 0; i < 32; i++) {
        v[i] -= mu;
        sq += v[i] * v[i];
    }
    #pragma unroll
    for (int o = 16; o; o >>= 1) sq += __shfl_xor_sync(0xffffffffu, sq, o);
    const float inv = rsqrtf(sq * (1.0f / D_MODEL) + 1e-6f);

    __half* yr = y + (size_t)row * D_MODEL;
    #pragma unroll
    for (int i = 0; i < 8; i++) {
        const int c = (i * 32 + lane) * 4;
        const float4 scv = *reinterpret_cast<const float4*>(sc + c);
        const float4 biv = *reinterpret_cast<const float4*>(bi + c);
        *reinterpret_cast<__half2*>(yr + c) =
            __floats2half2_rn(v[i*4+0] * inv * scv.x + biv.x, v[i*4+1] * inv * scv.y + biv.y);
        *reinterpret_cast<__half2*>(yr + c + 2) =
            __floats2half2_rn(v[i*4+2] * inv * scv.z + biv.z, v[i*4+3] * inv * scv.w + biv.w);
    }
}

// ========== merged weight convert: fp32 -> fp16, same [K][N] layout ==========
#define WQ4 (D_MODEL * 3 * D_MODEL / 4)
#define WO4 (D_MODEL * D_MODEL / 4)
#define W14 (D_MODEL * DFF / 4)
#define W24 (DFF * D_MODEL / 4)
#define WTOT4 (WQ4 + WO4 + W14 + W24)

__global__ void __launch_bounds__(256) convert_all(
    const float* __restrict__ wq, __half* __restrict__ oq,
    const float* __restrict__ wo, __half* __restrict__ oo,
    const float* __restrict__ w1, __half* __restrict__ o1,
    const float* __restrict__ w2, __half* __restrict__ o2)
{
    int i = blockIdx.x * 256 + threadIdx.x;
    if (i >= WTOT4) return;
    const float* src; __half* dst; int j = i;
    if (j < WQ4) { src = wq; dst = oq; }
    else if ((j -= WQ4) < WO4) { src = wo; dst = oo; }
    else if ((j -= WO4) < W14) { src = w1; dst = o1; }
    else { j -= W14; src = w2; dst = o2; }
    float4 v = reinterpret_cast<const float4*>(src)[j];
    *reinterpret_cast<__half2*>(dst + (size_t)j * 4)     = __floats2half2_rn(v.x, v.y);
    *reinterpret_cast<__half2*>(dst + (size_t)j * 4 + 2) = __floats2half2_rn(v.z, v.w);
}

// ================= fp16 GEMM via mma.sync: KC=64, 3-stage =================
#define KC 64
#define APAD 72                  /* A: fp16 elems per smem row (64 data + 8 pad) = 144B */
#define BROW 272                 /* B: bytes per smem row (256 data + 16 pad) */
#define OFF_A 0
#define OFF_B (128 * APAD * 2)               /* 18432 */
#define STAGE_BYTES (OFF_B + KC * BROW)      /* 35840 */
#define NSTAGE 3
#define GEMM_SMEM (NSTAGE * STAGE_BYTES)     /* 107520 */

__device__ __forceinline__ void load_chunk_h(
    uint32_t sbase, const __half* __restrict__ A, const __half* __restrict__ W,
    int m0, int n0, int N, int K, int k0, int tid)
{
    // A: 128 rows x 8 segs(16B) = 1024 cpa16 -> 4/thread
    #pragma unroll
    for (int j = 0; j < 4; j++) {
        int idx = tid + j * 256;
        int r = idx >> 3, sg = idx & 7;
        cpa16(sbase + OFF_A + (uint32_t)(r * (APAD * 2) + sg * 16),
              A + (size_t)(m0 + r) * K + k0 + sg * 8);
    }
    // B: 64 k-rows x 16 segs(16B) = 1024 cpa16 -> 4/thread
    #pragma unroll
    for (int j = 0; j < 4; j++) {
        int idx = tid + j * 256;
        int r = idx >> 4, sg = idx & 15;
        cpa16(sbase + OFF_B + (uint32_t)(r * BROW + sg * 16),
              W + (size_t)(k0 + r) * N + n0 + sg * 8);
    }
}

template<bool GELU_, bool RES_, bool HALFOUT>
__global__ void __launch_bounds__(256, 2) gemm_h(
    const __half* __restrict__ A, const __half* __restrict__ W,
    const float* __restrict__ bias, const float* __restrict__ Res,
    float* __restrict__ Cf, __half* __restrict__ Ch,
    int M, int N, int K)
{
    extern __shared__ char smem[];
    const uint32_t sb = smem_u32(smem);
    const int tid = threadIdx.x;
    const int wid = tid >> 5, lane = tid & 31;
    const int m0 = blockIdx.y * 128, n0 = blockIdx.x * 128;
    const int wm = (wid >> 2) * 64;
    const int wn = (wid & 3) * 32;

    const int a_r = lane & 15;
    const int a_c = (lane & 16) ? 8 : 0;
    const int b_row  = lane & 15;
    const int b_col8 = (lane & 16) ? 8 : 0;

    float c[4][4][4];
    #pragma unroll
    for (int i = 0; i < 4; i++)
        #pragma unroll
        for (int j = 0; j < 4; j++)
            #pragma unroll
            for (int e = 0; e < 4; e++) c[i][j][e] = 0.f;

    load_chunk_h(sb,               A, W, m0, n0, N, K, 0 * KC, tid);
    cp_commit();
    load_chunk_h(sb + STAGE_BYTES, A, W, m0, n0, N, K, 1 * KC, tid);
    cp_commit();

    const int NC = K / KC;
    int stage = 0;
    for (int i = 0; i < NC; i++) {
        if (i + 2 < NC) cp_wait1(); else cp_wait0();
        __syncthreads();
        if (i + 2 < NC) {
            int ls = stage + 2; if (ls >= NSTAGE) ls -= NSTAGE;
            load_chunk_h(sb + ls * STAGE_BYTES, A, W, m0, n0, N, K, (i + 2) * KC, tid);
            cp_commit();
        }
        const uint32_t st = sb + stage * STAGE_BYTES;
        const uint32_t aA = st + OFF_A + (wm + a_r) * (APAD * 2) + a_c * 2;
        #pragma unroll
        for (int kk = 0; kk < KC; kk += 16) {
            uint32_t af[4][4], bf[2][4];
            #pragma unroll
            for (int mt = 0; mt < 4; mt++)
                ldsm_x4(af[mt][0], af[mt][1], af[mt][2], af[mt][3],
                        aA + mt * 16 * (APAD * 2) + kk * 2);
            #pragma unroll
            for (int g = 0; g < 2; g++)
                ldsm_x4t(bf[g][0], bf[g][1], bf[g][2], bf[g][3],
                         st + OFF_B + (uint32_t)((kk + b_row) * BROW
                                                 + (wn + g * 16 + b_col8) * 2));
            #pragma unroll
            for (int mt = 0; mt < 4; mt++)
                #pragma unroll
                for (int nt = 0; nt < 4; nt++) {
                    const int g = nt >> 1, p = (nt & 1) * 2;
                    mma16816h(c[mt][nt], af[mt][0], af[mt][1], af[mt][2], af[mt][3],
                              bf[g][p], bf[g][p + 1]);
                }
        }
        stage++; if (stage >= NSTAGE) stage = 0;
    }

    const int t4 = lane >> 2, cp2 = (lane & 3) * 2;
    #pragma unroll
    for (int mt = 0; mt < 4; mt++) {
        #pragma unroll
        for (int half = 0; half < 2; half++) {
            const int row = m0 + wm + mt * 16 + t4 + half * 8;
            #pragma unroll
            for (int nt = 0; nt < 4; nt++) {
                const int col = n0 + wn + nt * 8 + cp2;
                float v0 = c[mt][nt][half * 2 + 0];
                float v1 = c[mt][nt][half * 2 + 1];
                const float2 bv = *reinterpret_cast<const float2*>(bias + col);
                v0 += bv.x; v1 += bv.y;
                if (GELU_) { v0 = gelu_tanh(v0); v1 = gelu_tanh(v1); }
                if (RES_) {
                    const float2 rv = *reinterpret_cast<const float2*>(
                        Res + (size_t)row * N + col);
                    v0 += rv.x; v1 += rv.y;
                }
                const size_t oof = (size_t)row * N + col;
                if (HALFOUT) {
                    *reinterpret_cast<__half2*>(Ch + oof) = __floats2half2_rn(v0, v1);
                } else {
                    float2 ov; ov.x = v0; ov.y = v1;
                    *reinterpret_cast<float2*>(Cf + oof) = ov;
                }
            }
        }
    }
}

// ============ Flash attention (R12 shape: 64-q-row CTA, 128 thr) ============
#define FRP 72
#define FQ 0
#define FKV(s) ((1 + 2 * (s)) * 64 * FRP)
#define FVV(s) ((2 + 2 * (s)) * 64 * FRP)
#define FA_SMEM (5 * 64 * FRP * 2)

__device__ __forceinline__ void fa_load_h(uint32_t dst, const __half* __restrict__ src, int tid)
{
    #pragma unroll
    for (int j = 0; j < 4; j++) {
        int idx = tid + j * 128;
        int r = idx >> 3, sg = idx & 7;
        cpa16(dst + (uint32_t)(r * (FRP * 2) + sg * 16),
              src + (size_t)r * 3072 + sg * 8);
    }
}

__global__ void __launch_bounds__(128) fa_kernel(
    const __half* __restrict__ qkv, __half* __restrict__ ctx)
{
    const int qt = (SEQ / 64 - 1) - blockIdx.x;   // longest-first
    const int h = blockIdx.y, b = blockIdx.z;
    const int q0 = qt * 64;
    extern __shared__ __half fsm[];
    const uint32_t sbase = smem_u32(fsm);
    const int tid = threadIdx.x;
    const int warp = tid >> 5, lane = tid & 31;
    const int t4 = lane >> 2, cp = (lane & 3) * 2;

    fa_load_h(sbase + FQ * 2, qkv + ((size_t)(b * SEQ + q0) * 3) * 1024 + h * 64, tid);
    fa_load_h(sbase + FKV(0) * 2, qkv + ((size_t)(b * SEQ) * 3 + 1) * 1024 + h * 64, tid);
    fa_load_h(sbase + FVV(0) * 2, qkv + ((size_t)(b * SEQ) * 3 + 2) * 1024 + h * 64, tid);
    cp_commit();

    const int a_r = lane & 15;
    const int a_c = (lane & 16) ? 8 : 0;
    const int b_r = (lane & 7) + ((lane & 16) ? 8 : 0);
    const int b_c = (lane & 8) ? 8 : 0;

    float o[8][4];
    #pragma unroll
    for (int i = 0; i < 8; i++)
        #pragma unroll
        for (int e = 0; e < 4; e++) o[i][e] = 0.f;
    float m0r = -1e30f, m1r = -1e30f, l0r = 0.f, l1r = 0.f;

    const int row0 = q0 + warp * 16 + t4;
    const int row1 = row0 + 8;

    uint32_t qf[4][4];
    bool qloaded = false;
    const __half2 qsc = __float2half2_rn(0.125f * 1.44269504f);

    for (int kt = 0; kt <= qt; kt++) {
        if (kt < qt) {
            fa_load_h(sbase + FKV((kt + 1) & 1) * 2,
                      qkv + ((size_t)(b * SEQ + (kt + 1) * 64) * 3 + 1) * 1024 + h * 64, tid);
            fa_load_h(sbase + FVV((kt + 1) & 1) * 2,
                      qkv + ((size_t)(b * SEQ + (kt + 1) * 64) * 3 + 2) * 1024 + h * 64, tid);
            cp_commit();
            cp_wait1();
        } else {
            cp_wait0();
        }
        __syncthreads();

        if (!qloaded) {
            qloaded = true;
            #pragma unroll
            for (int kk = 0; kk < 4; kk++) {
                ldsm_x4(qf[kk][0], qf[kk][1], qf[kk][2], qf[kk][3],
                        sbase + (uint32_t)(((warp * 16 + a_r) * FRP + kk * 16 + a_c) * 2) + FQ * 2);
                #pragma unroll
                for (int r = 0; r < 4; r++) {
                    __half2 hv = *reinterpret_cast<__half2*>(&qf[kk][r]);
                    hv = __hmul2(hv, qsc);
                    qf[kk][r] = *reinterpret_cast<uint32_t*>(&hv);
                }
            }
        }

        const uint32_t kb = sbase + FKV(kt & 1) * 2;
        const uint32_t vb = sbase + FVV(kt & 1) * 2;

        // ---- S = Q K^T (pre-scaled, base-2 domain) ----
        float c[8][4];
        #pragma unroll
        for (int i = 0; i < 8; i++)
            #pragma unroll
            for (int e = 0; e < 4; e++) c[i][e] = 0.f;
        #pragma unroll
        for (int kk = 0; kk < 4; kk++) {
            uint32_t kf[4][4];
            #pragma unroll
            for (int g = 0; g < 4; g++)
                ldsm_x4(kf[g][0], kf[g][1], kf[g][2], kf[g][3],
                        kb + (uint32_t)(((g * 16 + b_r) * FRP + kk * 16 + b_c) * 2));
            #pragma unroll
            for (int nt = 0; nt < 8; nt++) {
                const int g = nt >> 1, p = (nt & 1) * 2;
                mma16816h(c[nt], qf[kk][0], qf[kk][1], qf[kk][2], qf[kk][3],
                          kf[g][p], kf[g][p + 1]);
            }
        }

        // ---- causal mask ----
        if (kt == qt) {
            #pragma unroll
            for (int nt = 0; nt < 8; nt++) {
                const int colb = kt * 64 + nt * 8 + cp;
                #pragma unroll
                for (int e = 0; e < 4; e++) {
                    const int col = colb + (e & 1);
                    const int row = (e < 2) ? row0 : row1;
                    if (col > row) c[nt][e] = -1e30f;
                }
            }
        }

        // ---- online softmax (base-2) ----
        float mx0 = -1e30f, mx1 = -1e30f;
        #pragma unroll
        for (int nt = 0; nt < 8; nt++) {
            mx0 = fmaxf(mx0, fmaxf(c[nt][0], c[nt][1]));
            mx1 = fmaxf(mx1, fmaxf(c[nt][2], c[nt][3]));
        }
        mx0 = fmaxf(mx0, __shfl_xor_sync(0xffffffffu, mx0, 1));
        mx0 = fmaxf(mx0, __shfl_xor_sync(0xffffffffu, mx0, 2));
        mx1 = fmaxf(mx1, __shfl_xor_sync(0xffffffffu, mx1, 1));
        mx1 = fmaxf(mx1, __shfl_xor_sync(0xffffffffu, mx1, 2));
        const float mn0 = fmaxf(m0r, mx0), mn1 = fmaxf(m1r, mx1);
        const float al0 = ex2f(m0r - mn0), al1 = ex2f(m1r - mn1);
        m0r = mn0; m1r = mn1;
        float sum0 = 0.f, sum1 = 0.f;
        #pragma unroll
        for (int nt = 0; nt < 8; nt++) {
            float p0 = ex2f(c[nt][0] - mn0);
            float p1 = ex2f(c[nt][1] - mn0);
            float p2 = ex2f(c[nt][2] - mn1);
            float p3 = ex2f(c[nt][3] - mn1);
            c[nt][0] = p0; c[nt][1] = p1; c[nt][2] = p2; c[nt][3] = p3;
            sum0 += p0 + p1; sum1 += p2 + p3;
        }
        sum0 += __shfl_xor_sync(0xffffffffu, sum0, 1);
        sum0 += __shfl_xor_sync(0xffffffffu, sum0, 2);
        sum1 += __shfl_xor_sync(0xffffffffu, sum1, 1);
        sum1 += __shfl_xor_sync(0xffffffffu, sum1, 2);
        l0r = l0r * al0 + sum0;
        l1r = l1r * al1 + sum1;
        #pragma unroll
        for (int dt = 0; dt < 8; dt++) {
            o[dt][0] *= al0; o[dt][1] *= al0;
            o[dt][2] *= al1; o[dt][3] *= al1;
        }

        // ---- O += P V ----
        #pragma unroll
        for (int kt2 = 0; kt2 < 4; kt2++) {
            uint32_t pa[4];
            #pragma unroll
            for (int r = 0; r < 4; r++) {
                const int nt = 2 * kt2 + (r >> 1);
                const int e = (r & 1) * 2;
                pa[r] = pack_h2(c[nt][e], c[nt][e + 1]);
            }
            #pragma unroll
            for (int g2 = 0; g2 < 4; g2++) {
                uint32_t vr = vb +
                    (uint32_t)(((kt2 * 16 + ((lane & 8) ? 8 : 0) + (lane & 7)) * FRP
                                + g2 * 16 + ((lane & 16) ? 8 : 0)) * 2);
                uint32_t vf[4];
                ldsm_x4t(vf[0], vf[1], vf[2], vf[3], vr);
                mma16816h(o[2 * g2],     pa[0], pa[1], pa[2], pa[3], vf[0], vf[1]);
                mma16816h(o[2 * g2 + 1], pa[0], pa[1], pa[2], pa[3], vf[2], vf[3]);
            }
        }
        __syncthreads();
    }

    const float inv0 = 1.0f / l0r, inv1 = 1.0f / l1r;
    #pragma unroll
    for (int dt = 0; dt < 8; dt++) {
        const int col = h * 64 + dt * 8 + cp;
        *reinterpret_cast<__half2*>(ctx + (size_t)(b * SEQ + row0) * 1024 + col) =
            __floats2half2_rn(o[dt][0] * inv0, o[dt][1] * inv0);
        *reinterpret_cast<__half2*>(ctx + (size_t)(b * SEQ + row1) * 1024 + col) =
            __floats2half2_rn(o[dt][2] * inv1, o[dt][3] * inv1);
    }
}

// ================= launch =================
extern "C" void kernel_launch(void* const* d_in, const int* in_sizes, int n_in,
                              void* d_out, int out_size)
{
    const float* x      = (const float*)d_in[0];
    const float* w_qkv  = (const float*)d_in[1];
    const float* b_qkv  = (const float*)d_in[2];
    const float* w_out  = (const float*)d_in[3];
    const float* b_out  = (const float*)d_in[4];
    const float* w_fc1  = (const float*)d_in[5];
    const float* b_fc1  = (const float*)d_in[6];
    const float* w_fc2  = (const float*)d_in[7];
    const float* b_fc2  = (const float*)d_in[8];
    const float* ln1s   = (const float*)d_in[9];
    const float* ln1b   = (const float*)d_in[10];
    const float* ln2s   = (const float*)d_in[11];
    const float* ln2b   = (const float*)d_in[12];
    float* out = (float*)d_out;

    float *p_x1;
    __half *p_qkv, *p_ln, *p_ctx, *p_h, *p_wq, *p_wo, *p_w1, *p_w2;
    cudaGetSymbolAddress((void**)&p_qkv, g_qkv);
    cudaGetSymbolAddress((void**)&p_x1,  g_x1);
    cudaGetSymbolAddress((void**)&p_ln,  g_ln);
    cudaGetSymbolAddress((void**)&p_ctx, g_ctx);
    cudaGetSymbolAddress((void**)&p_h,   g_h);
    cudaGetSymbolAddress((void**)&p_wq,  g_wq);
    cudaGetSymbolAddress((void**)&p_wo,  g_wo);
    cudaGetSymbolAddress((void**)&p_w1,  g_w1);
    cudaGetSymbolAddress((void**)&p_w2,  g_w2);

    cudaFuncSetAttribute(gemm_h<false, false, true>,
                         cudaFuncAttributeMaxDynamicSharedMemorySize, GEMM_SMEM);
    cudaFuncSetAttribute(gemm_h<false, true, false>,
                         cudaFuncAttributeMaxDynamicSharedMemorySize, GEMM_SMEM);
    cudaFuncSetAttribute(gemm_h<true, false, true>,
                         cudaFuncAttributeMaxDynamicSharedMemorySize, GEMM_SMEM);
    cudaFuncSetAttribute(fa_kernel,
                         cudaFuncAttributeMaxDynamicSharedMemorySize, FA_SMEM);

    // 0) all weight converts in ONE launch
    convert_all<<<(WTOT4 + 255) / 256, 256>>>(w_qkv, p_wq, w_out, p_wo,
                                              w_fc1, p_w1, w_fc2, p_w2);
    // 1) LN1 -> fp16
    ln_kernel<<<MROWS / 8, 256>>>(x, ln1s, ln1b, p_ln);
    // 2) QKV projection -> fp16
    gemm_h<false, false, true><<<dim3(3072 / 128, MROWS / 128), 256, GEMM_SMEM>>>(
        p_ln, p_wq, b_qkv, nullptr, nullptr, p_qkv, MROWS, 3072, 1024);
    // 3) flash attention -> fp16 ctx
    fa_kernel<<<dim3(SEQ / 64, NH, BATCH), 128, FA_SMEM>>>(p_qkv, p_ctx);
    // 4) out projection + residual(x) -> fp32 x1
    gemm_h<false, true, false><<<dim3(1024 / 128, MROWS / 128), 256, GEMM_SMEM>>>(
        p_ctx, p_wo, b_out, x, p_x1, nullptr, MROWS, 1024, 1024);
    // 5) LN2 -> fp16
    ln_kernel<<<MROWS / 8, 256>>>(p_x1, ln2s, ln2b, p_ln);
    // 6) FC1 + GELU -> fp16
    gemm_h<true, false, true><<<dim3(4096 / 128, MROWS / 128), 256, GEMM_SMEM>>>(
        p_ln, p_w1, b_fc1, nullptr, nullptr, p_h, MROWS, 4096, 1024);
    // 7) FC2 + residual(x1) -> out (fp32)
    gemm_h<false, true, false><<<dim3(1024 / 128, MROWS / 128), 256, GEMM_SMEM>>>(
        p_h, p_w2, b_fc2, p_x1, out, nullptr, MROWS, 1024, 4096);
}